// round 1
// baseline (speedup 1.0000x reference)
#include <cuda_runtime.h>
#include <cuda_bf16.h>

// Problem constants (fixed by the reference: B=16384, L=512, 3 channels)
#define L_SEQ   512
#define NTHREADS 128           // 4 positions per thread
#define POS_PER_THREAD (L_SEQ / NTHREADS)
#define PAD_STANCE 3.0f

__global__ __launch_bounds__(NTHREADS, 8)
void crowd_kernel(const float* __restrict__ in,   // (B, 512, 3) fp32
                  const float* __restrict__ w,    // (1e6,) fp32
                  float* __restrict__ out,        // (6*B,) fp32: pre | dist | theta
                  int B)
{
    const int b   = blockIdx.x;
    const int tid = threadIdx.x;
    const int lane = tid & 31;
    const int wrp  = tid >> 5;

    // Each thread owns 4 contiguous positions: [4*tid, 4*tid+4).
    // Row = 1536 floats = 384 float4; thread t loads float4 indices 3t, 3t+1, 3t+2.
    const float4* src = reinterpret_cast<const float4*>(in) + (size_t)b * (3 * NTHREADS);
    float4 v0 = src[3 * tid + 0];
    float4 v1 = src[3 * tid + 1];
    float4 v2 = src[3 * tid + 2];

    // Demux interleaved (stance, col1, uid) for the 4 positions.
    float st[4], uidf[4];
    st[0] = v0.x;  uidf[0] = v0.z;
    st[1] = v0.w;  uidf[1] = v1.y;
    st[2] = v1.z;  uidf[2] = v2.x;
    st[3] = v2.y;  uidf[3] = v2.w;

    const int base_pos = tid * POS_PER_THREAD;

    // ---- Phase 1: first pad position (mask = pos < first_pad) ----
    int first_pad = L_SEQ;
    #pragma unroll
    for (int k = 0; k < POS_PER_THREAD; k++) {
        if (st[k] == PAD_STANCE) { first_pad = base_pos + k; break; }
    }
    // warp min
    #pragma unroll
    for (int off = 16; off > 0; off >>= 1)
        first_pad = min(first_pad, __shfl_xor_sync(0xFFFFFFFFu, first_pad, off));

    __shared__ int   s_min[NTHREADS / 32];
    __shared__ float s_real[NTHREADS / 32];
    __shared__ float s_fake[NTHREADS / 32];
    if (lane == 0) s_min[wrp] = first_pad;
    __syncthreads();
    int fp = s_min[0];
    #pragma unroll
    for (int i = 1; i < NTHREADS / 32; i++) fp = min(fp, s_min[i]);

    // ---- Phase 2: masked gather-sums ----
    float realp = 0.0f, fakep = 0.0f;
    #pragma unroll
    for (int k = 0; k < POS_PER_THREAD; k++) {
        int pos = base_pos + k;
        if (pos < fp) {
            float uw = __ldg(&w[(int)uidf[k]]);
            if (st[k] == 0.0f) realp += uw;
            else               fakep += uw;
        }
    }
    #pragma unroll
    for (int off = 16; off > 0; off >>= 1) {
        realp += __shfl_xor_sync(0xFFFFFFFFu, realp, off);
        fakep += __shfl_xor_sync(0xFFFFFFFFu, fakep, off);
    }
    if (lane == 0) { s_real[wrp] = realp; s_fake[wrp] = fakep; }
    __syncthreads();

    // ---- Epilogue: softmax + Beta moments (thread 0) ----
    if (tid == 0) {
        float rp = 0.0f, fq = 0.0f;
        #pragma unroll
        for (int i = 0; i < NTHREADS / 32; i++) { rp += s_real[i]; fq += s_fake[i]; }

        float n = (float)fp;                    // response_num
        float m  = fmaxf(rp, fq);
        float e0 = __expf(rp - m);
        float e1 = __expf(fq - m);
        float inv = 1.0f / (e0 + e1);
        float pre0 = e0 * inv;                  // user_pre[:,0] (real)
        float pre1 = e1 * inv;                  // user_pre[:,1] (fake)

        float th0 = pre0 * n;                   // user_theta[:,0] -> beta_b
        float th1 = pre1 * n;                   // user_theta[:,1] -> beta_a
        float a = th1, bb = th0;
        float s = a + bb;
        float mean = a / s;
        float var  = (a * bb) / (s * s * (s + 1.0f));

        // Output layout: tuple-flatten (user_pre, user_distribution, user_theta)
        out[(size_t)b * 2 + 0]               = pre0;
        out[(size_t)b * 2 + 1]               = pre1;
        out[(size_t)2 * B + (size_t)b * 2 + 0] = mean;
        out[(size_t)2 * B + (size_t)b * 2 + 1] = sqrtf(var);
        out[(size_t)4 * B + (size_t)b * 2 + 0] = th0;
        out[(size_t)4 * B + (size_t)b * 2 + 1] = th1;
    }
}

extern "C" void kernel_launch(void* const* d_in, const int* in_sizes, int n_in,
                              void* d_out, int out_size)
{
    const float* in = (const float*)d_in[0];   // (B, 512, 3) fp32
    const float* w  = (const float*)d_in[1];   // (1e6,) fp32
    float* out = (float*)d_out;

    int B = in_sizes[0] / (L_SEQ * 3);

    crowd_kernel<<<B, NTHREADS>>>(in, w, out, B);
}